// round 6
// baseline (speedup 1.0000x reference)
#include <cuda_runtime.h>
#include <cuda_bf16.h>
#include <cstdint>
#include <math.h>

namespace {
constexpr int TT = 4096;   // tokens (B*S)
constexpr int DD = 1024;   // model dim
constexpr int EE = 8;      // experts
constexpr int FF = 4096;   // ffn dim
}

// ---------------- device scratch (no runtime allocation allowed) -----------
__device__ int g_expert_id[TT];
__device__ int g_counts[EE];
__device__ int g_offsets[EE];
__device__ int g_cursor[EE];
__device__ int g_perm[TT];
__device__ __nv_bfloat16 g_x_hi[(size_t)TT * DD];        // 8 MB
__device__ __nv_bfloat16 g_x_lo[(size_t)TT * DD];        // 8 MB
__device__ __nv_bfloat16 g_h_hi[(size_t)TT * FF];        // 32 MB
__device__ __nv_bfloat16 g_h_lo[(size_t)TT * FF];        // 32 MB
__device__ __nv_bfloat16 g_w1_hi[(size_t)EE * DD * FF];  // 64 MB
__device__ __nv_bfloat16 g_w1_lo[(size_t)EE * DD * FF];  // 64 MB
__device__ __nv_bfloat16 g_w2_hi[(size_t)EE * FF * DD];  // 64 MB
__device__ __nv_bfloat16 g_w2_lo[(size_t)EE * FF * DD];  // 64 MB

// ---------------- helpers ---------------------------------------------------
__device__ __forceinline__ uint32_t smem_u32(const void* p) {
    uint32_t a;
    asm("{ .reg .u64 t; cvta.to.shared.u64 t, %1; cvt.u32.u64 %0, t; }" : "=r"(a) : "l"(p));
    return a;
}
// fp32 -> bf16 (hi, lo) split, packed as bf16x2 pairs
__device__ __forceinline__ void split2(float a, float b, uint32_t& hi, uint32_t& lo) {
    __nv_bfloat16 ha = __float2bfloat16(a);
    __nv_bfloat16 hb = __float2bfloat16(b);
    __nv_bfloat16 la = __float2bfloat16(a - __bfloat162float(ha));
    __nv_bfloat16 lb = __float2bfloat16(b - __bfloat162float(hb));
    __nv_bfloat162 ph; ph.x = ha; ph.y = hb;
    __nv_bfloat162 pl; pl.x = la; pl.y = lb;
    hi = *reinterpret_cast<uint32_t*>(&ph);
    lo = *reinterpret_cast<uint32_t*>(&pl);
}
__device__ __forceinline__ float gelu_exact(float x) {
    return 0.5f * x * (1.0f + erff(x * 0.70710678118654752f));
}
__device__ __forceinline__ void cpa16(uint32_t dst, const void* src, uint32_t sz) {
    asm volatile("cp.async.cg.shared.global [%0], [%1], 16, %2;"
                 :: "r"(dst), "l"(src), "r"(sz) : "memory");
}
#define CP_COMMIT() asm volatile("cp.async.commit_group;" ::: "memory")
#define CP_WAIT0()  asm volatile("cp.async.wait_group 0;" ::: "memory")
#define LDSM4(r, addr)                                                           \
    asm volatile("ldmatrix.sync.aligned.m8n8.x4.shared.b16 {%0,%1,%2,%3}, [%4];" \
                 : "=r"((r)[0]), "=r"((r)[1]), "=r"((r)[2]), "=r"((r)[3])        \
                 : "r"(addr))
#define LDSM4T(r, addr)                                                          \
    asm volatile("ldmatrix.sync.aligned.m8n8.x4.trans.shared.b16 {%0,%1,%2,%3}, [%4];" \
                 : "=r"((r)[0]), "=r"((r)[1]), "=r"((r)[2]), "=r"((r)[3])        \
                 : "r"(addr))
#define MMA_BF16(d, a, b0, b1)                                                   \
    asm volatile("mma.sync.aligned.m16n8k16.row.col.f32.bf16.bf16.f32 "          \
                 "{%0,%1,%2,%3}, {%4,%5,%6,%7}, {%8,%9}, {%0,%1,%2,%3};"         \
                 : "+f"((d)[0]), "+f"((d)[1]), "+f"((d)[2]), "+f"((d)[3])        \
                 : "r"((a)[0]), "r"((a)[1]), "r"((a)[2]), "r"((a)[3]),           \
                   "r"(b0), "r"(b1))

// ---------------- preconversion (fp32 -> bf16 hi/lo, same layout) -----------
__device__ __forceinline__ void conv_one(const float* src, __nv_bfloat16* hi,
                                         __nv_bfloat16* lo) {
    const size_t i = (size_t)blockIdx.x * blockDim.x + threadIdx.x;   // float4 idx
    const float4 v = reinterpret_cast<const float4*>(src)[i];
    uint32_t h0, l0, h1, l1;
    split2(v.x, v.y, h0, l0);
    split2(v.z, v.w, h1, l1);
    reinterpret_cast<uint2*>(hi)[i] = make_uint2(h0, h1);
    reinterpret_cast<uint2*>(lo)[i] = make_uint2(l0, l1);
}
__global__ void conv_x_k (const float* __restrict__ s) { conv_one(s, g_x_hi,  g_x_lo); }
__global__ void conv_w1_k(const float* __restrict__ s) { conv_one(s, g_w1_hi, g_w1_lo); }
__global__ void conv_w2_k(const float* __restrict__ s) { conv_one(s, g_w2_hi, g_w2_lo); }

// ---------------- bookkeeping (proven, unchanged) ----------------------------
__global__ void moe_init() {
    if (threadIdx.x < EE) g_counts[threadIdx.x] = 0;
}

__global__ void moe_router(const float* __restrict__ x, const float* __restrict__ gw) {
    __shared__ float sg[EE * DD];
    for (int i = threadIdx.x; i < EE * DD; i += blockDim.x) sg[i] = gw[i];
    __syncthreads();
    const int warp = threadIdx.x >> 5, lane = threadIdx.x & 31;
    const int token = blockIdx.x * 8 + warp;
    const float* xr = x + (size_t)token * DD;
    float acc[EE];
    #pragma unroll
    for (int e = 0; e < EE; e++) acc[e] = 0.f;
    for (int k = lane; k < DD; k += 32) {
        const float xv = xr[k];
        #pragma unroll
        for (int e = 0; e < EE; e++) acc[e] = fmaf(xv, sg[e * DD + k], acc[e]);
    }
    #pragma unroll
    for (int e = 0; e < EE; e++) {
        #pragma unroll
        for (int off = 16; off > 0; off >>= 1)
            acc[e] += __shfl_xor_sync(0xffffffffu, acc[e], off);
    }
    if (lane == 0) {
        int best = 0; float bv = acc[0];
        #pragma unroll
        for (int e = 1; e < EE; e++)
            if (acc[e] > bv) { bv = acc[e]; best = e; }   // first-max = jnp.argmax
        g_expert_id[token] = best;
        atomicAdd(&g_counts[best], 1);
    }
}

__global__ void moe_scan() {
    if (threadIdx.x == 0) {
        int s = 0;
        for (int e = 0; e < EE; e++) { g_offsets[e] = s; g_cursor[e] = s; s += g_counts[e]; }
    }
}

__global__ void moe_scatter() {
    const int t = blockIdx.x * blockDim.x + threadIdx.x;
    if (t >= TT) return;
    const int e = g_expert_id[t];
    g_perm[atomicAdd(&g_cursor[e], 1)] = t;
}

// ---------------- grouped GEMM: CTA 128M x 256N, warp 64x64, cp.async x2 ----
// All operands pre-split bf16 hi/lo in GMEM. 3-MMA fp32 emu (hi*hi+lo*hi+hi*lo).
// SMEM per stage (24 KB): Ah[4K] Al[4K] Bh[8K] Bl[8K], two stages = 48 KB.
// Tile-contiguous layout: 8x(8x16B) 128-byte ldmatrix tiles, conflict-free,
// no padding. A tiles: (row>>3)*256 + kb*128 + (row&7)*16 (kb = 8-k block).
// B tiles: (k>>3)*4096 + nchunk*128 + (k&7)*16 (nchunk = 8-n block of 16B).
// PHASE1: A = g_x rows gathered via perm; epilogue GELU+split -> g_h hi/lo.
// PHASE2: A = g_h rows (permuted space); epilogue scatters fp32 to Out.
template<int PHASE>
__global__ __launch_bounds__(256, 1) void moe_gemm_mma(float* __restrict__ Out) {
    constexpr int KDIM = (PHASE == 1) ? DD : FF;
    constexpr int NDIM = (PHASE == 1) ? FF : DD;
    __shared__ __align__(128) char sm[49152];

    const int e   = blockIdx.z;
    const int cnt = g_counts[e];
    const int m0  = blockIdx.x * 128;
    if (m0 >= cnt) return;
    const int off = g_offsets[e];
    const int n0  = blockIdx.y * 256;
    const uint32_t sb = smem_u32(sm);

    const int tid = threadIdx.x, lane = tid & 31, wid = tid >> 5;
    const int warpM = wid >> 2, warpN = wid & 3;   // 2 x 4 warps, 64x64 tiles

    const __nv_bfloat16* Ahi = (PHASE == 1) ? g_x_hi : g_h_hi;
    const __nv_bfloat16* Alo = (PHASE == 1) ? g_x_lo : g_h_lo;
    const __nv_bfloat16* Bhi = (PHASE == 1) ? g_w1_hi : g_w2_hi;
    const __nv_bfloat16* Blo = (PHASE == 1) ? g_w1_lo : g_w2_lo;

    // ---- cp.async source setup ----
    // A: thread -> (row = tid>>1, kb = tid&1); 1 hi + 1 lo chunk of 16B
    const int rowA = tid >> 1, kbA = tid & 1;
    const bool vA = (m0 + rowA) < cnt;
    size_t aRow;
    if (PHASE == 1) aRow = vA ? (size_t)g_perm[off + m0 + rowA] : 0;
    else            aRow = (size_t)(off + m0 + (vA ? rowA : 0));
    const __nv_bfloat16* aHs = Ahi + aRow * KDIM + kbA * 8;
    const __nv_bfloat16* aLs = Alo + aRow * KDIM + kbA * 8;
    const uint32_t aSz = vA ? 16u : 0u;
    const uint32_t aDo = (uint32_t)(rowA >> 3) * 256 + (uint32_t)kbA * 128
                       + (uint32_t)(rowA & 7) * 16;
    // B: thread -> (k = tid>>4, nchunks tid&15 and tid&15+16); 2 hi + 2 lo
    const int kB = tid >> 4, ncB = tid & 15;
    const size_t bBase = (size_t)e * KDIM * NDIM + (size_t)kB * NDIM + n0 + ncB * 8;
    const __nv_bfloat16* bHs = Bhi + bBase;
    const __nv_bfloat16* bLs = Blo + bBase;
    const uint32_t bDo = 8192u + (uint32_t)(kB >> 3) * 4096 + (uint32_t)ncB * 128
                       + (uint32_t)(kB & 7) * 16;

    auto prefetch = [&](int s) {
        const uint32_t base = sb + (uint32_t)(s & 1) * 24576;
        const int k0 = s * 16;
        cpa16(base + aDo,        aHs + k0, aSz);
        cpa16(base + aDo + 4096, aLs + k0, aSz);
        const size_t bk = (size_t)k0 * NDIM;
        cpa16(base + bDo,               bHs + bk,       16u);
        cpa16(base + bDo + 2048,        bHs + bk + 128, 16u);
        cpa16(base + bDo + 8192,        bLs + bk,       16u);
        cpa16(base + bDo + 8192 + 2048, bLs + bk + 128, 16u);
        CP_COMMIT();
    };

    // ---- ldmatrix per-thread offsets (same lane->element maps as validated) --
    uint32_t aOff[4], bOff[4];
    #pragma unroll
    for (int mf = 0; mf < 4; ++mf) {
        const int row = warpM * 64 + mf * 16 + (lane & 15);
        aOff[mf] = (uint32_t)(row >> 3) * 256 + (uint32_t)(lane >> 4) * 128
                 + (uint32_t)(row & 7) * 16;
    }
    #pragma unroll
    for (int nq = 0; nq < 4; ++nq) {
        const int kr = lane & 15;
        const int c  = warpN * 8 + nq * 2 + (lane >> 4);
        bOff[nq] = 8192u + (uint32_t)(kr >> 3) * 4096 + (uint32_t)c * 128
                 + (uint32_t)(kr & 7) * 16;
    }

    float acc[4][8][4];
    #pragma unroll
    for (int a = 0; a < 4; ++a)
        #pragma unroll
        for (int b = 0; b < 8; ++b)
            #pragma unroll
            for (int c = 0; c < 4; ++c) acc[a][b][c] = 0.f;

    constexpr int NS = KDIM / 16;
    prefetch(0);

    for (int s = 0; s < NS; ++s) {
        CP_WAIT0();
        __syncthreads();
        if (s + 1 < NS) prefetch(s + 1);

        const uint32_t base = sb + (uint32_t)(s & 1) * 24576;
        uint32_t ah[4][4], al[4][4];
        #pragma unroll
        for (int mf = 0; mf < 4; ++mf) {
            LDSM4(ah[mf], base + aOff[mf]);
            LDSM4(al[mf], base + aOff[mf] + 4096);
        }
        #pragma unroll
        for (int nq = 0; nq < 4; ++nq) {
            uint32_t bh[4], bl[4];
            LDSM4T(bh, base + bOff[nq]);
            LDSM4T(bl, base + bOff[nq] + 8192);
            #pragma unroll
            for (int mf = 0; mf < 4; ++mf)
                #pragma unroll
                for (int hh = 0; hh < 2; ++hh) {
                    float* d = acc[mf][nq * 2 + hh];
                    MMA_BF16(d, ah[mf], bh[2 * hh], bh[2 * hh + 1]);
                    MMA_BF16(d, al[mf], bh[2 * hh], bh[2 * hh + 1]);
                    MMA_BF16(d, ah[mf], bl[2 * hh], bl[2 * hh + 1]);
                }
        }
    }

    // ---- epilogue ----
    const int rB = m0 + warpM * 64 + (lane >> 2);
    const int cB = n0 + warpN * 64 + (lane & 3) * 2;
    #pragma unroll
    for (int mf = 0; mf < 4; ++mf) {
        #pragma unroll
        for (int rr = 0; rr < 2; ++rr) {
            const int gr = rB + mf * 16 + rr * 8;
            if (gr >= cnt) continue;
            if (PHASE == 1) {
                const size_t rowoff = (size_t)(off + gr) * NDIM;
                #pragma unroll
                for (int nf = 0; nf < 8; ++nf) {
                    const float f0 = gelu_exact(acc[mf][nf][rr * 2 + 0]);
                    const float f1 = gelu_exact(acc[mf][nf][rr * 2 + 1]);
                    uint32_t h, l;
                    split2(f0, f1, h, l);
                    *reinterpret_cast<uint32_t*>(g_h_hi + rowoff + cB + nf * 8) = h;
                    *reinterpret_cast<uint32_t*>(g_h_lo + rowoff + cB + nf * 8) = l;
                }
            } else {
                const int tok = g_perm[off + gr];
                float* dst = Out + (size_t)tok * DD + cB;
                #pragma unroll
                for (int nf = 0; nf < 8; ++nf)
                    *reinterpret_cast<float2*>(dst + nf * 8) =
                        make_float2(acc[mf][nf][rr * 2 + 0], acc[mf][nf][rr * 2 + 1]);
            }
        }
    }
}

// ---------------- launch ----------------------------------------------------
extern "C" void kernel_launch(void* const* d_in, const int* in_sizes, int n_in,
                              void* d_out, int out_size) {
    (void)in_sizes; (void)n_in; (void)out_size;
    const float* x  = (const float*)d_in[0];
    const float* gw = (const float*)d_in[1];
    const float* w1 = (const float*)d_in[2];   // [E][D][F]
    const float* w2 = (const float*)d_in[3];   // [E][F][D]
    float* out = (float*)d_out;

    // preconversion to bf16 hi/lo (elementwise, DRAM-bound)
    conv_x_k <<<(TT * DD / 4) / 256, 256>>>(x);
    conv_w1_k<<<((size_t)EE * DD * FF / 4) / 256, 256>>>(w1);
    conv_w2_k<<<((size_t)EE * FF * DD / 4) / 256, 256>>>(w2);

    // routing
    moe_init<<<1, 32>>>();
    moe_router<<<TT / 8, 256>>>(x, gw);
    moe_scan<<<1, 1>>>();
    moe_scatter<<<TT / 256, 256>>>();

    // GEMM1: h = gelu(x_gathered @ w1[e]); N=4096 -> 16 n-tiles of 256
    moe_gemm_mma<1><<<dim3(32, FF / 256, EE), 256>>>(nullptr);
    // GEMM2: out = h @ w2[e] scattered; N=1024 -> 4 n-tiles of 256
    moe_gemm_mma<2><<<dim3(32, DD / 256, EE), 256>>>(out);
}